// round 14
// baseline (speedup 1.0000x reference)
#include <cuda_runtime.h>
#include <cuda_bf16.h>
#include <cstdint>

#define B_   128
#define S_   512
#define E_   300
#define KP   320     // padded K for GEMM
#define H_   128
#define G4   512     // 4*H
#define T_   12
#define SOS_ 3
#define EOS_ 4
#define NEGV (-10000.0f)

// fused-kernel geometry
#define NPROD 100            // producer (GEMM) blocks
#define NCONS 32             // consumer (LSTM) blocks
#define NTILES 4096          // 512 by-tiles x 8 bx-tiles

// ---------------- scratch (static device allocations) ----------------
__device__ __align__(16) __nv_bfloat16 g_emb[(size_t)B_*S_*KP];   // [65536][320]
__device__ __align__(16) __nv_bfloat16 g_wcat[1024*KP];           // [1024][320]
__device__ __align__(16) __nv_bfloat16 g_whh[2*G4*H_];            // [2][512][128]
__device__ float g_bias[1024];
__device__ float g_pre[(size_t)2*B_*S_*G4];                       // [2][128][512][512] fp32
__device__ __align__(16) __nv_bfloat16 g_hcat[(size_t)B_*S_*2*H_]; // [65536][256] bf16
__device__ int g_tile_ctr;
__device__ int g_chunk_cnt[512];   // per (b*4 + q): #bx tiles done (target 8)

// ---------------- helpers ----------------
__device__ __forceinline__ float tanhapx(float x) {
    float r; asm("tanh.approx.f32 %0, %1;" : "=f"(r) : "f"(x)); return r;
}
__device__ __forceinline__ float sigf(float x) {
    return 0.5f + 0.5f * tanhapx(0.5f * x);
}
__device__ __forceinline__ void cp16(void* smem, const void* gmem) {
    uint32_t s = (uint32_t)__cvta_generic_to_shared(smem);
    asm volatile("cp.async.cg.shared.global [%0], [%1], 16;\n" :: "r"(s), "l"(gmem) : "memory");
}
__device__ __forceinline__ void cp_commit() {
    asm volatile("cp.async.commit_group;\n" ::: "memory");
}
template<int N> __device__ __forceinline__ void cp_wait() {
    asm volatile("cp.async.wait_group %0;\n" :: "n"(N) : "memory");
}

// ---------------- K1: embedding gather -> bf16, K-padded (vectorized) ----------------
__global__ void k_prep_emb(const int* __restrict__ x, const float* __restrict__ embed) {
    const int row = blockIdx.x;
    const int p   = threadIdx.x;
    const int xv  = x[row];
    __nv_bfloat162 v;
    if (p < E_ / 2) {
        float2 f = *(const float2*)&embed[(size_t)xv * E_ + p * 2];
        v = __floats2bfloat162_rn(f.x, f.y);
    } else {
        v = __floats2bfloat162_rn(0.0f, 0.0f);
    }
    *(__nv_bfloat162*)&g_emb[(size_t)row * KP + p * 2] = v;
}

// ---------------- K1b: weight packing ----------------
__global__ void k_prep_w(const float* __restrict__ Wih_f, const float* __restrict__ Whh_f,
                         const float* __restrict__ b_f,
                         const float* __restrict__ Wih_b, const float* __restrict__ Whh_b,
                         const float* __restrict__ b_b) {
    int idx = blockIdx.x * blockDim.x + threadIdx.x;
    const int NW = 1024 * KP;
    const int NH = 2 * G4 * H_;
    if (idx < NW) {
        int r = idx / KP, k = idx % KP;
        float v = 0.0f;
        if (k < E_) v = (r < G4) ? Wih_f[r * E_ + k] : Wih_b[(r - G4) * E_ + k];
        g_wcat[idx] = __float2bfloat16(v);
    } else if (idx < NW + NH) {
        int i = idx - NW;
        int d = i / (G4 * H_);
        int rem = i % (G4 * H_);
        float v = d ? Whh_b[rem] : Whh_f[rem];
        g_whh[i] = __float2bfloat16(v);
    } else if (idx < NW + NH + 1024) {
        int n = idx - NW - NH;
        g_bias[n] = (n < G4) ? b_f[n] : b_b[n - G4];
    }
}

// ---------------- K1c: reset flags (each launch -> replay-deterministic) ----------------
__global__ void k_reset() {
    if (threadIdx.x == 0) g_tile_ctr = 0;
    g_chunk_cnt[threadIdx.x] = 0;
}

// ---------------- K2: fused producer(GEMM)/consumer(LSTM) ----------------
#define BM 128
#define BN 128
#define BK 32
#define SA 40
#define KITERS (KP / BK)   // 10
#define HS 136             // h_sm row stride in bf16

__global__ __launch_bounds__(512, 1) void k_main() {
    __shared__ __align__(16) char s_raw[40960];   // union: GEMM As/Bs  |  LSTM h_sm
    __shared__ int s_ti;

    const int bid = blockIdx.x;
    const int tid = threadIdx.x;

    if (bid < NPROD) {
        // ============ GEMM producer (work-stealing, 512 threads, 16 warps 4x4) ============
        __nv_bfloat16 (*As)[BM * SA] = (__nv_bfloat16(*)[BM * SA])s_raw;
        __nv_bfloat16 (*Bs)[BN * SA] = (__nv_bfloat16(*)[BN * SA])(s_raw + 2 * BM * SA * 2);

        const int warp = tid >> 5, lane = tid & 31;
        const int wm = warp >> 2, wn = warp & 3;       // 4m x 4n, warp tile 32x32
        const int lr = lane >> 2, lc = (lane & 3) * 2;
        const int ldr = tid >> 2, seg = tid & 3;
        const int lg = lane >> 3, lr8 = lane & 7;

        uint32_t aAddr[2][2], bAddr[2][2];
        #pragma unroll
        for (int st = 0; st < 2; st++) {
            #pragma unroll
            for (int mi = 0; mi < 2; mi++) {
                const int arow = wm * 32 + mi * 16 + lr8 + (lg & 1) * 8;
                const int acol = (lg >> 1) * 8;
                aAddr[st][mi] = (uint32_t)__cvta_generic_to_shared(&As[st][arow * SA + acol]);
            }
            #pragma unroll
            for (int kh = 0; kh < 2; kh++) {
                const int brow = wn * 32 + lg * 8 + lr8;
                bAddr[st][kh] = (uint32_t)__cvta_generic_to_shared(&Bs[st][brow * SA + kh * 8]);
            }
        }

        __syncthreads();
        if (tid == 0) s_ti = atomicAdd(&g_tile_ctr, 1);
        __syncthreads();
        int ti = s_ti;

        while (ti < NTILES) {
            // tile decode: phase A = chunks {0,3} (b-interleaved), phase B = {1,2}
            int b, q, bx;
            if (ti < 2048) {
                b = ti >> 4; int sub = ti & 15; q = (sub < 8) ? 0 : 3; bx = sub & 7;
            } else {
                int r2 = ti - 2048; b = r2 >> 4; int sub = r2 & 15; q = (sub < 8) ? 1 : 2; bx = sub & 7;
            }
            const int m0 = b * 512 + q * 128;
            const int n0 = bx * 128;
            const int fb = b * 4 + q;

            float acc[2][4][4];
            #pragma unroll
            for (int a = 0; a < 2; a++)
                #pragma unroll
                for (int bb2 = 0; bb2 < 4; bb2++)
                    #pragma unroll
                    for (int c = 0; c < 4; c++) acc[a][bb2][c] = 0.0f;

            // prologue: stage 0
            cp16(&As[0][ldr * SA + seg * 8], &g_emb[(size_t)(m0 + ldr) * KP + seg * 8]);
            cp16(&Bs[0][ldr * SA + seg * 8], &g_wcat[(size_t)(n0 + ldr) * KP + seg * 8]);
            cp_commit();

            for (int it = 0; it < KITERS; it++) {
                if (it + 1 < KITERS) {
                    const int kt = (it + 1) * BK;
                    const int st = (it + 1) & 1;
                    cp16(&As[st][ldr * SA + seg * 8], &g_emb[(size_t)(m0 + ldr) * KP + kt + seg * 8]);
                    cp16(&Bs[st][ldr * SA + seg * 8], &g_wcat[(size_t)(n0 + ldr) * KP + kt + seg * 8]);
                    cp_commit();
                    cp_wait<1>();
                } else {
                    cp_wait<0>();
                }
                __syncthreads();
                const int st = it & 1;
                #pragma unroll
                for (int ks = 0; ks < 2; ks++) {
                    const uint32_t koff = (uint32_t)(ks * 16) * 2;
                    uint32_t a[2][4];
                    #pragma unroll
                    for (int mi = 0; mi < 2; mi++)
                        asm volatile("ldmatrix.sync.aligned.m8n8.x4.shared.b16 {%0,%1,%2,%3}, [%4];\n"
                                     : "=r"(a[mi][0]), "=r"(a[mi][1]), "=r"(a[mi][2]), "=r"(a[mi][3])
                                     : "r"(aAddr[st][mi] + koff));
                    uint32_t bfr[4][2];
                    #pragma unroll
                    for (int kh = 0; kh < 2; kh++)
                        asm volatile("ldmatrix.sync.aligned.m8n8.x4.shared.b16 {%0,%1,%2,%3}, [%4];\n"
                                     : "=r"(bfr[0][kh]), "=r"(bfr[1][kh]),
                                       "=r"(bfr[2][kh]), "=r"(bfr[3][kh])
                                     : "r"(bAddr[st][kh] + koff));
                    #pragma unroll
                    for (int mi = 0; mi < 2; mi++)
                        #pragma unroll
                        for (int ni = 0; ni < 4; ni++) {
                            asm volatile(
                                "mma.sync.aligned.m16n8k16.row.col.f32.bf16.bf16.f32 "
                                "{%0,%1,%2,%3}, {%4,%5,%6,%7}, {%8,%9}, {%0,%1,%2,%3};\n"
                                : "+f"(acc[mi][ni][0]), "+f"(acc[mi][ni][1]),
                                  "+f"(acc[mi][ni][2]), "+f"(acc[mi][ni][3])
                                : "r"(a[mi][0]), "r"(a[mi][1]), "r"(a[mi][2]), "r"(a[mi][3]),
                                  "r"(bfr[ni][0]), "r"(bfr[ni][1]));
                        }
                }
                __syncthreads();
            }
            // epilogue: bias + scatter fp32 PRE
            #pragma unroll
            for (int mi = 0; mi < 2; mi++) {
                #pragma unroll
                for (int ni = 0; ni < 4; ni++) {
                    int m = m0 + wm * 32 + mi * 16 + lr;
                    int n = n0 + wn * 32 + ni * 8 + lc;
                    int d = n >> 9, j = n & 511;
                    float bias0 = g_bias[n], bias1 = g_bias[n + 1];
                    {
                        int bb = m >> 9, ss = m & 511;
                        size_t base = (((size_t)(d * B_ + bb) * S_ + ss) * G4 + j);
                        *(float2*)&g_pre[base] = make_float2(acc[mi][ni][0] + bias0,
                                                             acc[mi][ni][1] + bias1);
                    }
                    {
                        int m2 = m + 8;
                        int bb = m2 >> 9, ss = m2 & 511;
                        size_t base = (((size_t)(d * B_ + bb) * S_ + ss) * G4 + j);
                        *(float2*)&g_pre[base] = make_float2(acc[mi][ni][2] + bias0,
                                                             acc[mi][ni][3] + bias1);
                    }
                }
            }
            __threadfence();
            __syncthreads();
            if (tid == 0) {
                atomicAdd(&g_chunk_cnt[fb], 1);
                s_ti = atomicAdd(&g_tile_ctr, 1);
            }
            __syncthreads();
            ti = s_ti;
        }
    } else {
        // ============ LSTM consumer (proven R13 kernel + chunk waits) ============
        __nv_bfloat16 (*h_sm)[16][HS] = (__nv_bfloat16(*)[16][HS])s_raw;

        const int lbid = bid - NPROD;
        const int d   = lbid >> 4;
        const int bg  = lbid & 15;
        const int b0  = bg * 8;
        const int w = tid >> 5, l = tid & 31;
        const int r = l >> 2, cpair = (l & 3) * 2;

        uint32_t Bf[4][8][2];
        #pragma unroll
        for (int ni = 0; ni < 4; ni++) {
            const int n = w * 8 + ni * 128 + r;
            const __nv_bfloat16* src = &g_whh[((size_t)d * G4 + n) * H_ + cpair];
            #pragma unroll
            for (int tk = 0; tk < 8; tk++) {
                Bf[ni][tk][0] = *(const uint32_t*)&src[tk * 16];
                Bf[ni][tk][1] = *(const uint32_t*)&src[tk * 16 + 8];
            }
        }
        for (int i = tid; i < 2 * 16 * HS; i += 512)
            ((__nv_bfloat16*)h_sm)[i] = __float2bfloat16(0.0f);

        const int b  = b0 + r;
        const int m0 = w * 8 + cpair;
        const int sgn = d ? -1 : 1;
        const int se0 = d ? (S_ - 1) : 0;

        const float* preb = &g_pre[((size_t)(d * B_ + b) * S_ + se0) * G4 + m0];
        __nv_bfloat16* hout = &g_hcat[((size_t)b * S_ + se0) * 256 + d * H_ + m0];
        const int preb_step = sgn * G4;
        const int hout_step = sgn * 256;

        __syncthreads();

        // wait for first chunk of all 8 batches
        {
            const int qc = d ? 3 : 0;
            if (tid < 8) {
                volatile int* cnt = (volatile int*)&g_chunk_cnt[(b0 + tid) * 4 + qc];
                while (*cnt < 8) { }
            }
            __syncthreads();
            __threadfence();
        }

        float2 pf[4];
        #pragma unroll
        for (int ni = 0; ni < 4; ni++)
            pf[ni] = *(const float2*)&preb[ni * 128];

        float cA = 0.0f, cB = 0.0f;
        const uint32_t abase0 =
            (uint32_t)__cvta_generic_to_shared(&h_sm[0][l & 15][(l >> 4) * 8]);

        int buf = 0;
        #pragma unroll 1
        for (int s = 0; s < S_; s++) {
            float acc[4][4];
            #pragma unroll
            for (int ni = 0; ni < 4; ni++) {
                acc[ni][0] = pf[ni].x; acc[ni][1] = pf[ni].y;
                acc[ni][2] = 0.0f;     acc[ni][3] = 0.0f;
            }
            // chunk-boundary wait covers the prefetch of step s+1
            if ((s & 127) == 127 && s != S_ - 1) {
                const int qn = d ? ((510 - s) >> 7) : ((s + 1) >> 7);
                if (tid < 8) {
                    volatile int* cnt = (volatile int*)&g_chunk_cnt[(b0 + tid) * 4 + qn];
                    while (*cnt < 8) { }
                }
                __syncthreads();
                __threadfence();
            }
            if (s < S_ - 1) preb += preb_step;
            #pragma unroll
            for (int ni = 0; ni < 4; ni++)
                pf[ni] = *(const float2*)&preb[ni * 128];

            const uint32_t abase = abase0 + (uint32_t)buf * (16 * HS * 2);
            #pragma unroll
            for (int tk = 0; tk < 8; tk++) {
                uint32_t a0, a1, a2, a3;
                asm volatile("ldmatrix.sync.aligned.m8n8.x4.shared.b16 {%0,%1,%2,%3}, [%4];\n"
                             : "=r"(a0), "=r"(a1), "=r"(a2), "=r"(a3)
                             : "r"(abase + tk * 32));
                #pragma unroll
                for (int ni = 0; ni < 4; ni++) {
                    asm volatile(
                        "mma.sync.aligned.m16n8k16.row.col.f32.bf16.bf16.f32 "
                        "{%0,%1,%2,%3}, {%4,%5,%6,%7}, {%8,%9}, {%0,%1,%2,%3};\n"
                        : "+f"(acc[ni][0]), "+f"(acc[ni][1]),
                          "+f"(acc[ni][2]), "+f"(acc[ni][3])
                        : "r"(a0), "r"(a1), "r"(a2), "r"(a3),
                          "r"(Bf[ni][tk][0]), "r"(Bf[ni][tk][1]));
                }
            }

            cA = sigf(acc[1][0]) * cA + sigf(acc[0][0]) * tanhapx(acc[2][0]);
            cB = sigf(acc[1][1]) * cB + sigf(acc[0][1]) * tanhapx(acc[2][1]);
            float hA = sigf(acc[3][0]) * tanhapx(cA);
            float hB = sigf(acc[3][1]) * tanhapx(cB);

            __nv_bfloat162 hpk = __floats2bfloat162_rn(hA, hB);
            *(__nv_bfloat162*)&h_sm[buf ^ 1][r][m0] = hpk;
            *(__nv_bfloat162*)hout = hpk;
            hout += hout_step;

            __syncthreads();
            buf ^= 1;
        }
    }
}

// ---------------- K4: fused output linear + CRF forward + gold (unchanged) ----------------
__global__ __launch_bounds__(128) void k_outcrf(const int* __restrict__ y0,
                                                const float* __restrict__ trans,
                                                const float* __restrict__ Wout,
                                                const float* __restrict__ bout,
                                                float* __restrict__ out) {
    __shared__ float ysm[S_][T_];
    __shared__ float wsm[T_][256];
    __shared__ float tsm[T_][T_];
    __shared__ float esm[T_][T_];
    __shared__ float gpart[3];
    __shared__ float zsm;

    const int b = blockIdx.x;
    const int tid = threadIdx.x;
    const int lane = tid & 31, wrp = tid >> 5;

    for (int i = tid; i < T_ * 256; i += 128) wsm[0][i] = Wout[i];
    for (int i = tid; i < T_ * T_; i += 128) {
        float tv = trans[i];
        tsm[0][i] = tv;
        esm[0][i] = __expf(tv);
    }
    if (tid < 3) gpart[tid] = 0.0f;
    __syncthreads();

    const __nv_bfloat162* hbase = (const __nv_bfloat162*)&g_hcat[(size_t)b * S_ * 256];
    for (int idx = tid; idx < S_ * T_; idx += 128) {
        const int s = idx / T_, t = idx - s * T_;
        const __nv_bfloat162* hp = hbase + s * 128;
        const float2* wp = (const float2*)&wsm[t][0];
        float acc = bout[t];
        #pragma unroll 16
        for (int q = 0; q < 128; q++) {
            float2 h2 = __bfloat1622float2(hp[q]);
            float2 w2 = wp[q];
            acc += h2.x * w2.x + h2.y * w2.y;
        }
        ysm[s][t] = acc;
    }
    __syncthreads();

    if (wrp > 0) {
        const int* yb = &y0[b * S_];
        float g = 0.0f;
        for (int s = tid - 32; s < S_; s += 96) {
            int cur = yb[s];
            int prev = s ? yb[s - 1] : SOS_;
            g += ysm[s][cur] + tsm[cur][prev];
        }
        #pragma unroll
        for (int o = 16; o; o >>= 1) g += __shfl_xor_sync(0xffffffffu, g, o);
        if (lane == 0) gpart[wrp - 1] = g;
    } else {
        float e_row[T_];
        const int irow = (lane < T_) ? lane : 0;
        #pragma unroll
        for (int jj = 0; jj < T_; jj++) e_row[jj] = esm[irow][jj];

        float score = (lane < T_) ? tsm[irow][SOS_] + ysm[0][irow] : -1e30f;

        for (int s = 1; s < S_; s++) {
            float anchor = __shfl_sync(0xffffffffu, score, 0);
            float p = __expf(score - anchor);
            float Ssum = 0.0f;
            #pragma unroll
            for (int jj = 0; jj < T_; jj++)
                Ssum = fmaf(e_row[jj], __shfl_sync(0xffffffffu, p, jj), Ssum);
            float yv = ysm[s][irow];
            score = (lane < T_) ? anchor + __logf(Ssum) + yv : -1e30f;
        }
        float vz = (lane < T_) ? score + tsm[EOS_][irow] : -1e30f;
        float mz = vz;
        #pragma unroll
        for (int o = 16; o; o >>= 1) mz = fmaxf(mz, __shfl_xor_sync(0xffffffffu, mz, o));
        float ez = (lane < T_) ? __expf(vz - mz) : 0.0f;
        #pragma unroll
        for (int o = 16; o; o >>= 1) ez += __shfl_xor_sync(0xffffffffu, ez, o);
        if (lane == 0) zsm = mz + __logf(ez);
    }
    __syncthreads();
    if (tid == 0) {
        const int last = y0[b * S_ + S_ - 1];
        float gold = gpart[0] + gpart[1] + gpart[2] + tsm[EOS_][last];
        out[b] = zsm - gold;
    }
}

// ---------------- launcher ----------------
extern "C" void kernel_launch(void* const* d_in, const int* in_sizes, int n_in,
                              void* d_out, int out_size) {
    const int*   x     = (const int*)d_in[0];
    const int*   y0    = (const int*)d_in[1];
    const float* embed = (const float*)d_in[2];
    const float* Wih_f = (const float*)d_in[3];
    const float* Whh_f = (const float*)d_in[4];
    const float* b_f   = (const float*)d_in[5];
    const float* Wih_b = (const float*)d_in[6];
    const float* Whh_b = (const float*)d_in[7];
    const float* b_b   = (const float*)d_in[8];
    const float* Wout  = (const float*)d_in[9];
    const float* bout  = (const float*)d_in[10];
    const float* trans = (const float*)d_in[11];
    float* out = (float*)d_out;

    k_prep_emb<<<B_ * S_, KP / 2>>>(x, embed);

    const int prep_total = 1024 * KP + 2 * G4 * H_ + 1024;
    k_prep_w<<<(prep_total + 255) / 256, 256>>>(Wih_f, Whh_f, b_f, Wih_b, Whh_b, b_b);

    k_reset<<<1, 512>>>();

    k_main<<<NPROD + NCONS, 512>>>();

    k_outcrf<<<B_, 128>>>(y0, trans, Wout, bout, out);
}

// round 16
// speedup vs baseline: 1.0346x; 1.0346x over previous
#include <cuda_runtime.h>
#include <cuda_bf16.h>
#include <cstdint>

#define B_   128
#define S_   512
#define E_   300
#define KP   320     // padded K for GEMM
#define H_   128
#define G4   512     // 4*H
#define T_   12
#define SOS_ 3
#define EOS_ 4
#define NEGV (-10000.0f)

// fused-kernel geometry
#define NPROD 100            // producer (GEMM) blocks
#define NCONS 32             // consumer (LSTM) blocks
#define NTILES 4096          // 512 by-tiles x 8 bx-tiles

// ---------------- scratch (static device allocations) ----------------
__device__ __align__(16) __nv_bfloat16 g_emb[(size_t)B_*S_*KP];   // [65536][320]
__device__ __align__(16) __nv_bfloat16 g_wcat[1024*KP];           // [1024][320]
__device__ __align__(16) __nv_bfloat16 g_whh[2*G4*H_];            // [2][512][128]
__device__ float g_bias[1024];
__device__ float g_pre[(size_t)2*B_*S_*G4];                       // [2][128][512][512] fp32
__device__ __align__(16) __nv_bfloat16 g_hcat[(size_t)B_*S_*2*H_]; // [65536][256] bf16
__device__ int g_tile_ctr;
__device__ int g_chunk_cnt[512];   // per (b*4 + q): #bx tiles done (target 8)

// ---------------- helpers ----------------
__device__ __forceinline__ float tanhapx(float x) {
    float r; asm("tanh.approx.f32 %0, %1;" : "=f"(r) : "f"(x)); return r;
}
__device__ __forceinline__ float sigf(float x) {
    return 0.5f + 0.5f * tanhapx(0.5f * x);
}
__device__ __forceinline__ void cp16(void* smem, const void* gmem) {
    uint32_t s = (uint32_t)__cvta_generic_to_shared(smem);
    asm volatile("cp.async.cg.shared.global [%0], [%1], 16;\n" :: "r"(s), "l"(gmem) : "memory");
}
__device__ __forceinline__ void cp_commit() {
    asm volatile("cp.async.commit_group;\n" ::: "memory");
}
template<int N> __device__ __forceinline__ void cp_wait() {
    asm volatile("cp.async.wait_group %0;\n" :: "n"(N) : "memory");
}

// ---------------- K1: embedding gather -> bf16 (16 rows/block, MLP=10) ----------------
__global__ __launch_bounds__(256) void k_prep_emb(const int* __restrict__ x,
                                                  const float* __restrict__ embed) {
    const int row = blockIdx.x * 16 + (threadIdx.x >> 4);   // 16 rows per block
    const int j   = threadIdx.x & 15;                       // 16 threads per row
    const int xv  = x[row];
    const float* src = &embed[(size_t)xv * E_];
    __nv_bfloat16* dst = &g_emb[(size_t)row * KP];
    #pragma unroll
    for (int i = 0; i < 10; i++) {
        const int p = j + i * 16;            // pair index 0..159
        __nv_bfloat162 v;
        if (p < E_ / 2) {
            float2 f = *(const float2*)&src[p * 2];
            v = __floats2bfloat162_rn(f.x, f.y);
        } else {
            v = __floats2bfloat162_rn(0.0f, 0.0f);
        }
        *(__nv_bfloat162*)&dst[p * 2] = v;
    }
}

// ---------------- K1b: weight packing + flag reset ----------------
__global__ void k_prep_w(const float* __restrict__ Wih_f, const float* __restrict__ Whh_f,
                         const float* __restrict__ b_f,
                         const float* __restrict__ Wih_b, const float* __restrict__ Whh_b,
                         const float* __restrict__ b_b) {
    int idx = blockIdx.x * blockDim.x + threadIdx.x;
    const int NW = 1024 * KP;
    const int NH = 2 * G4 * H_;
    if (idx < NW) {
        int r = idx / KP, k = idx % KP;
        float v = 0.0f;
        if (k < E_) v = (r < G4) ? Wih_f[r * E_ + k] : Wih_b[(r - G4) * E_ + k];
        g_wcat[idx] = __float2bfloat16(v);
    } else if (idx < NW + NH) {
        int i = idx - NW;
        int d = i / (G4 * H_);
        int rem = i % (G4 * H_);
        float v = d ? Whh_b[rem] : Whh_f[rem];
        g_whh[i] = __float2bfloat16(v);
    } else if (idx < NW + NH + 1024) {
        int n = idx - NW - NH;
        g_bias[n] = (n < G4) ? b_f[n] : b_b[n - G4];
    } else if (idx < NW + NH + 1024 + 512) {
        g_chunk_cnt[idx - NW - NH - 1024] = 0;
    } else if (idx == NW + NH + 1024 + 512) {
        g_tile_ctr = 0;
    }
}

// ---------------- K2: fused producer(GEMM)/consumer(LSTM) — unchanged from R14 ----------------
#define BM 128
#define BN 128
#define BK 32
#define SA 40
#define KITERS (KP / BK)   // 10
#define HS 136             // h_sm row stride in bf16

__global__ __launch_bounds__(512, 1) void k_main() {
    __shared__ __align__(16) char s_raw[40960];   // union: GEMM As/Bs  |  LSTM h_sm
    __shared__ int s_ti;

    const int bid = blockIdx.x;
    const int tid = threadIdx.x;

    if (bid < NPROD) {
        // ============ GEMM producer (work-stealing, 512 threads, 16 warps 4x4) ============
        __nv_bfloat16 (*As)[BM * SA] = (__nv_bfloat16(*)[BM * SA])s_raw;
        __nv_bfloat16 (*Bs)[BN * SA] = (__nv_bfloat16(*)[BN * SA])(s_raw + 2 * BM * SA * 2);

        const int warp = tid >> 5, lane = tid & 31;
        const int wm = warp >> 2, wn = warp & 3;       // 4m x 4n, warp tile 32x32
        const int lr = lane >> 2, lc = (lane & 3) * 2;
        const int ldr = tid >> 2, seg = tid & 3;
        const int lg = lane >> 3, lr8 = lane & 7;

        uint32_t aAddr[2][2], bAddr[2][2];
        #pragma unroll
        for (int st = 0; st < 2; st++) {
            #pragma unroll
            for (int mi = 0; mi < 2; mi++) {
                const int arow = wm * 32 + mi * 16 + lr8 + (lg & 1) * 8;
                const int acol = (lg >> 1) * 8;
                aAddr[st][mi] = (uint32_t)__cvta_generic_to_shared(&As[st][arow * SA + acol]);
            }
            #pragma unroll
            for (int kh = 0; kh < 2; kh++) {
                const int brow = wn * 32 + lg * 8 + lr8;
                bAddr[st][kh] = (uint32_t)__cvta_generic_to_shared(&Bs[st][brow * SA + kh * 8]);
            }
        }

        __syncthreads();
        if (tid == 0) s_ti = atomicAdd(&g_tile_ctr, 1);
        __syncthreads();
        int ti = s_ti;

        while (ti < NTILES) {
            int b, q, bx;
            if (ti < 2048) {
                b = ti >> 4; int sub = ti & 15; q = (sub < 8) ? 0 : 3; bx = sub & 7;
            } else {
                int r2 = ti - 2048; b = r2 >> 4; int sub = r2 & 15; q = (sub < 8) ? 1 : 2; bx = sub & 7;
            }
            const int m0 = b * 512 + q * 128;
            const int n0 = bx * 128;
            const int fb = b * 4 + q;

            float acc[2][4][4];
            #pragma unroll
            for (int a = 0; a < 2; a++)
                #pragma unroll
                for (int bb2 = 0; bb2 < 4; bb2++)
                    #pragma unroll
                    for (int c = 0; c < 4; c++) acc[a][bb2][c] = 0.0f;

            cp16(&As[0][ldr * SA + seg * 8], &g_emb[(size_t)(m0 + ldr) * KP + seg * 8]);
            cp16(&Bs[0][ldr * SA + seg * 8], &g_wcat[(size_t)(n0 + ldr) * KP + seg * 8]);
            cp_commit();

            for (int it = 0; it < KITERS; it++) {
                if (it + 1 < KITERS) {
                    const int kt = (it + 1) * BK;
                    const int st = (it + 1) & 1;
                    cp16(&As[st][ldr * SA + seg * 8], &g_emb[(size_t)(m0 + ldr) * KP + kt + seg * 8]);
                    cp16(&Bs[st][ldr * SA + seg * 8], &g_wcat[(size_t)(n0 + ldr) * KP + kt + seg * 8]);
                    cp_commit();
                    cp_wait<1>();
                } else {
                    cp_wait<0>();
                }
                __syncthreads();
                const int st = it & 1;
                #pragma unroll
                for (int ks = 0; ks < 2; ks++) {
                    const uint32_t koff = (uint32_t)(ks * 16) * 2;
                    uint32_t a[2][4];
                    #pragma unroll
                    for (int mi = 0; mi < 2; mi++)
                        asm volatile("ldmatrix.sync.aligned.m8n8.x4.shared.b16 {%0,%1,%2,%3}, [%4];\n"
                                     : "=r"(a[mi][0]), "=r"(a[mi][1]), "=r"(a[mi][2]), "=r"(a[mi][3])
                                     : "r"(aAddr[st][mi] + koff));
                    uint32_t bfr[4][2];
                    #pragma unroll
                    for (int kh = 0; kh < 2; kh++)
                        asm volatile("ldmatrix.sync.aligned.m8n8.x4.shared.b16 {%0,%1,%2,%3}, [%4];\n"
                                     : "=r"(bfr[0][kh]), "=r"(bfr[1][kh]),
                                       "=r"(bfr[2][kh]), "=r"(bfr[3][kh])
                                     : "r"(bAddr[st][kh] + koff));
                    #pragma unroll
                    for (int mi = 0; mi < 2; mi++)
                        #pragma unroll
                        for (int ni = 0; ni < 4; ni++) {
                            asm volatile(
                                "mma.sync.aligned.m16n8k16.row.col.f32.bf16.bf16.f32 "
                                "{%0,%1,%2,%3}, {%4,%5,%6,%7}, {%8,%9}, {%0,%1,%2,%3};\n"
                                : "+f"(acc[mi][ni][0]), "+f"(acc[mi][ni][1]),
                                  "+f"(acc[mi][ni][2]), "+f"(acc[mi][ni][3])
                                : "r"(a[mi][0]), "r"(a[mi][1]), "r"(a[mi][2]), "r"(a[mi][3]),
                                  "r"(bfr[ni][0]), "r"(bfr[ni][1]));
                        }
                }
                __syncthreads();
            }
            #pragma unroll
            for (int mi = 0; mi < 2; mi++) {
                #pragma unroll
                for (int ni = 0; ni < 4; ni++) {
                    int m = m0 + wm * 32 + mi * 16 + lr;
                    int n = n0 + wn * 32 + ni * 8 + lc;
                    int d = n >> 9, j = n & 511;
                    float bias0 = g_bias[n], bias1 = g_bias[n + 1];
                    {
                        int bb = m >> 9, ss = m & 511;
                        size_t base = (((size_t)(d * B_ + bb) * S_ + ss) * G4 + j);
                        *(float2*)&g_pre[base] = make_float2(acc[mi][ni][0] + bias0,
                                                             acc[mi][ni][1] + bias1);
                    }
                    {
                        int m2 = m + 8;
                        int bb = m2 >> 9, ss = m2 & 511;
                        size_t base = (((size_t)(d * B_ + bb) * S_ + ss) * G4 + j);
                        *(float2*)&g_pre[base] = make_float2(acc[mi][ni][2] + bias0,
                                                             acc[mi][ni][3] + bias1);
                    }
                }
            }
            __threadfence();
            __syncthreads();
            if (tid == 0) {
                atomicAdd(&g_chunk_cnt[fb], 1);
                s_ti = atomicAdd(&g_tile_ctr, 1);
            }
            __syncthreads();
            ti = s_ti;
        }
    } else {
        // ============ LSTM consumer (proven kernel + chunk waits) ============
        __nv_bfloat16 (*h_sm)[16][HS] = (__nv_bfloat16(*)[16][HS])s_raw;

        const int lbid = bid - NPROD;
        const int d   = lbid >> 4;
        const int bg  = lbid & 15;
        const int b0  = bg * 8;
        const int w = tid >> 5, l = tid & 31;
        const int r = l >> 2, cpair = (l & 3) * 2;

        uint32_t Bf[4][8][2];
        #pragma unroll
        for (int ni = 0; ni < 4; ni++) {
            const int n = w * 8 + ni * 128 + r;
            const __nv_bfloat16* src = &g_whh[((size_t)d * G4 + n) * H_ + cpair];
            #pragma unroll
            for (int tk = 0; tk < 8; tk++) {
                Bf[ni][tk][0] = *(const uint32_t*)&src[tk * 16];
                Bf[ni][tk][1] = *(const uint32_t*)&src[tk * 16 + 8];
            }
        }
        for (int i = tid; i < 2 * 16 * HS; i += 512)
            ((__nv_bfloat16*)h_sm)[i] = __float2bfloat16(0.0f);

        const int b  = b0 + r;
        const int m0 = w * 8 + cpair;
        const int sgn = d ? -1 : 1;
        const int se0 = d ? (S_ - 1) : 0;

        const float* preb = &g_pre[((size_t)(d * B_ + b) * S_ + se0) * G4 + m0];
        __nv_bfloat16* hout = &g_hcat[((size_t)b * S_ + se0) * 256 + d * H_ + m0];
        const int preb_step = sgn * G4;
        const int hout_step = sgn * 256;

        __syncthreads();

        {
            const int qc = d ? 3 : 0;
            if (tid < 8) {
                volatile int* cnt = (volatile int*)&g_chunk_cnt[(b0 + tid) * 4 + qc];
                while (*cnt < 8) { }
            }
            __syncthreads();
            __threadfence();
        }

        float2 pf[4];
        #pragma unroll
        for (int ni = 0; ni < 4; ni++)
            pf[ni] = *(const float2*)&preb[ni * 128];

        float cA = 0.0f, cB = 0.0f;
        const uint32_t abase0 =
            (uint32_t)__cvta_generic_to_shared(&h_sm[0][l & 15][(l >> 4) * 8]);

        int buf = 0;
        #pragma unroll 1
        for (int s = 0; s < S_; s++) {
            float acc[4][4];
            #pragma unroll
            for (int ni = 0; ni < 4; ni++) {
                acc[ni][0] = pf[ni].x; acc[ni][1] = pf[ni].y;
                acc[ni][2] = 0.0f;     acc[ni][3] = 0.0f;
            }
            if ((s & 127) == 127 && s != S_ - 1) {
                const int qn = d ? ((510 - s) >> 7) : ((s + 1) >> 7);
                if (tid < 8) {
                    volatile int* cnt = (volatile int*)&g_chunk_cnt[(b0 + tid) * 4 + qn];
                    while (*cnt < 8) { }
                }
                __syncthreads();
                __threadfence();
            }
            if (s < S_ - 1) preb += preb_step;
            #pragma unroll
            for (int ni = 0; ni < 4; ni++)
                pf[ni] = *(const float2*)&preb[ni * 128];

            const uint32_t abase = abase0 + (uint32_t)buf * (16 * HS * 2);
            #pragma unroll
            for (int tk = 0; tk < 8; tk++) {
                uint32_t a0, a1, a2, a3;
                asm volatile("ldmatrix.sync.aligned.m8n8.x4.shared.b16 {%0,%1,%2,%3}, [%4];\n"
                             : "=r"(a0), "=r"(a1), "=r"(a2), "=r"(a3)
                             : "r"(abase + tk * 32));
                #pragma unroll
                for (int ni = 0; ni < 4; ni++) {
                    asm volatile(
                        "mma.sync.aligned.m16n8k16.row.col.f32.bf16.bf16.f32 "
                        "{%0,%1,%2,%3}, {%4,%5,%6,%7}, {%8,%9}, {%0,%1,%2,%3};\n"
                        : "+f"(acc[ni][0]), "+f"(acc[ni][1]),
                          "+f"(acc[ni][2]), "+f"(acc[ni][3])
                        : "r"(a0), "r"(a1), "r"(a2), "r"(a3),
                          "r"(Bf[ni][tk][0]), "r"(Bf[ni][tk][1]));
                }
            }

            cA = sigf(acc[1][0]) * cA + sigf(acc[0][0]) * tanhapx(acc[2][0]);
            cB = sigf(acc[1][1]) * cB + sigf(acc[0][1]) * tanhapx(acc[2][1]);
            float hA = sigf(acc[3][0]) * tanhapx(cA);
            float hB = sigf(acc[3][1]) * tanhapx(cB);

            __nv_bfloat162 hpk = __floats2bfloat162_rn(hA, hB);
            *(__nv_bfloat162*)&h_sm[buf ^ 1][r][m0] = hpk;
            *(__nv_bfloat162*)hout = hpk;
            hout += hout_step;

            __syncthreads();
            buf ^= 1;
        }
    }
}

// ---------------- K4: fused output linear + CRF forward + gold (256 threads) ----------------
__global__ __launch_bounds__(256) void k_outcrf(const int* __restrict__ y0,
                                                const float* __restrict__ trans,
                                                const float* __restrict__ Wout,
                                                const float* __restrict__ bout,
                                                float* __restrict__ out) {
    __shared__ float ysm[S_][T_];        // 24576 B
    __shared__ float wsm[T_][256];       // 12288 B
    __shared__ float tsm[T_][T_];
    __shared__ float esm[T_][T_];
    __shared__ float gpart[7];
    __shared__ float zsm;

    const int b = blockIdx.x;
    const int tid = threadIdx.x;
    const int lane = tid & 31, wrp = tid >> 5;

    for (int i = tid; i < T_ * 256; i += 256) wsm[0][i] = Wout[i];
    for (int i = tid; i < T_ * T_; i += 256) {
        float tv = trans[i];
        tsm[0][i] = tv;
        esm[0][i] = __expf(tv);    // exp(-1e4) = 0 exactly
    }
    if (tid < 7) gpart[tid] = 0.0f;
    __syncthreads();

    // ---- Phase 1: y = hcat @ Wout^T + bout ----
    const __nv_bfloat162* hbase = (const __nv_bfloat162*)&g_hcat[(size_t)b * S_ * 256];
    for (int idx = tid; idx < S_ * T_; idx += 256) {
        const int s = idx / T_, t = idx - s * T_;
        const __nv_bfloat162* hp = hbase + s * 128;
        const float2* wp = (const float2*)&wsm[t][0];
        float acc = bout[t];
        #pragma unroll 16
        for (int q = 0; q < 128; q++) {
            float2 h2 = __bfloat1622float2(hp[q]);
            float2 w2 = wp[q];
            acc += h2.x * w2.x + h2.y * w2.y;
        }
        ysm[s][t] = acc;
    }
    __syncthreads();

    // ---- Phase 2a: warps 1-7 compute gold path score ----
    if (wrp > 0) {
        const int* yb = &y0[b * S_];
        float g = 0.0f;
        for (int s = tid - 32; s < S_; s += 224) {
            int cur = yb[s];
            int prev = s ? yb[s - 1] : SOS_;
            g += ysm[s][cur] + tsm[cur][prev];
        }
        #pragma unroll
        for (int o = 16; o; o >>= 1) g += __shfl_xor_sync(0xffffffffu, g, o);
        if (lane == 0) gpart[wrp - 1] = g;
    }
    // ---- Phase 2b: warp 0 forward scan (exp-domain, lane-0 anchor) ----
    else {
        float e_row[T_];
        const int irow = (lane < T_) ? lane : 0;
        #pragma unroll
        for (int jj = 0; jj < T_; jj++) e_row[jj] = esm[irow][jj];

        float score = (lane < T_) ? tsm[irow][SOS_] + ysm[0][irow] : -1e30f;

        for (int s = 1; s < S_; s++) {
            float anchor = __shfl_sync(0xffffffffu, score, 0);
            float p = __expf(score - anchor);
            float Ssum = 0.0f;
            #pragma unroll
            for (int jj = 0; jj < T_; jj++)
                Ssum = fmaf(e_row[jj], __shfl_sync(0xffffffffu, p, jj), Ssum);
            float yv = ysm[s][irow];
            score = (lane < T_) ? anchor + __logf(Ssum) + yv : -1e30f;
        }
        float vz = (lane < T_) ? score + tsm[EOS_][irow] : -1e30f;
        float mz = vz;
        #pragma unroll
        for (int o = 16; o; o >>= 1) mz = fmaxf(mz, __shfl_xor_sync(0xffffffffu, mz, o));
        float ez = (lane < T_) ? __expf(vz - mz) : 0.0f;
        #pragma unroll
        for (int o = 16; o; o >>= 1) ez += __shfl_xor_sync(0xffffffffu, ez, o);
        if (lane == 0) zsm = mz + __logf(ez);
    }
    __syncthreads();
    if (tid == 0) {
        const int last = y0[b * S_ + S_ - 1];
        float gold = gpart[0] + gpart[1] + gpart[2] + gpart[3] + gpart[4] + gpart[5] + gpart[6]
                   + tsm[EOS_][last];
        out[b] = zsm - gold;
    }
}

// ---------------- launcher ----------------
extern "C" void kernel_launch(void* const* d_in, const int* in_sizes, int n_in,
                              void* d_out, int out_size) {
    const int*   x     = (const int*)d_in[0];
    const int*   y0    = (const int*)d_in[1];
    const float* embed = (const float*)d_in[2];
    const float* Wih_f = (const float*)d_in[3];
    const float* Whh_f = (const float*)d_in[4];
    const float* b_f   = (const float*)d_in[5];
    const float* Wih_b = (const float*)d_in[6];
    const float* Whh_b = (const float*)d_in[7];
    const float* b_b   = (const float*)d_in[8];
    const float* Wout  = (const float*)d_in[9];
    const float* bout  = (const float*)d_in[10];
    const float* trans = (const float*)d_in[11];
    float* out = (float*)d_out;

    k_prep_emb<<<(B_ * S_) / 16, 256>>>(x, embed);

    const int prep_total = 1024 * KP + 2 * G4 * H_ + 1024 + 512 + 1;
    k_prep_w<<<(prep_total + 255) / 256, 256>>>(Wih_f, Whh_f, b_f, Wih_b, Whh_b, b_b);

    k_main<<<NPROD + NCONS, 512>>>();

    k_outcrf<<<B_, 256>>>(y0, trans, Wout, bout, out);
}

// round 17
// speedup vs baseline: 1.1911x; 1.1513x over previous
#include <cuda_runtime.h>
#include <cuda_bf16.h>
#include <cstdint>

#define B_   128
#define S_   512
#define E_   300
#define KP   320     // padded K for GEMM
#define H_   128
#define G4   512     // 4*H
#define T_   12
#define SOS_ 3
#define EOS_ 4
#define NEGV (-10000.0f)

// fused-kernel geometry
#define NPROD 100            // producer (GEMM) blocks
#define NCONS 32             // consumer (LSTM) blocks
#define NTILES 4096          // 512 by-tiles x 8 bx-tiles

// ---------------- scratch (static device allocations) ----------------
__device__ __align__(16) __nv_bfloat16 g_emb[(size_t)B_*S_*KP];   // [65536][320]
__device__ __align__(16) __nv_bfloat16 g_wcat[1024*KP];           // [1024][320]
__device__ __align__(16) __nv_bfloat16 g_whh[2*G4*H_];            // [2][512][128]
__device__ float g_bias[1024];
__device__ float g_pre[(size_t)2*B_*S_*G4];                       // [2][128][512][512] fp32
__device__ __align__(16) __nv_bfloat16 g_hcat[(size_t)B_*S_*2*H_]; // [65536][256] bf16
__device__ int g_tile_ctr;
__device__ int g_chunk_cnt[512];   // per (b*4 + q): #bx tiles done (target 8)

// ---------------- helpers ----------------
__device__ __forceinline__ float tanhapx(float x) {
    float r; asm("tanh.approx.f32 %0, %1;" : "=f"(r) : "f"(x)); return r;
}
__device__ __forceinline__ float sigf(float x) {
    return 0.5f + 0.5f * tanhapx(0.5f * x);
}
__device__ __forceinline__ void cp16(void* smem, const void* gmem) {
    uint32_t s = (uint32_t)__cvta_generic_to_shared(smem);
    asm volatile("cp.async.cg.shared.global [%0], [%1], 16;\n" :: "r"(s), "l"(gmem) : "memory");
}
__device__ __forceinline__ void cp_commit() {
    asm volatile("cp.async.commit_group;\n" ::: "memory");
}
template<int N> __device__ __forceinline__ void cp_wait() {
    asm volatile("cp.async.wait_group %0;\n" :: "n"(N) : "memory");
}

// ---------------- K1: embedding gather -> bf16 (16 rows/block, MLP=10) ----------------
__global__ __launch_bounds__(256) void k_prep_emb(const int* __restrict__ x,
                                                  const float* __restrict__ embed) {
    const int row = blockIdx.x * 16 + (threadIdx.x >> 4);   // 16 rows per block
    const int j   = threadIdx.x & 15;                       // 16 threads per row
    const int xv  = x[row];
    const float* src = &embed[(size_t)xv * E_];
    __nv_bfloat16* dst = &g_emb[(size_t)row * KP];
    #pragma unroll
    for (int i = 0; i < 10; i++) {
        const int p = j + i * 16;            // pair index 0..159
        __nv_bfloat162 v;
        if (p < E_ / 2) {
            float2 f = *(const float2*)&src[p * 2];
            v = __floats2bfloat162_rn(f.x, f.y);
        } else {
            v = __floats2bfloat162_rn(0.0f, 0.0f);
        }
        *(__nv_bfloat162*)&dst[p * 2] = v;
    }
}

// ---------------- K1b: weight packing + flag reset ----------------
__global__ void k_prep_w(const float* __restrict__ Wih_f, const float* __restrict__ Whh_f,
                         const float* __restrict__ b_f,
                         const float* __restrict__ Wih_b, const float* __restrict__ Whh_b,
                         const float* __restrict__ b_b) {
    int idx = blockIdx.x * blockDim.x + threadIdx.x;
    const int NW = 1024 * KP;
    const int NH = 2 * G4 * H_;
    if (idx < NW) {
        int r = idx / KP, k = idx % KP;
        float v = 0.0f;
        if (k < E_) v = (r < G4) ? Wih_f[r * E_ + k] : Wih_b[(r - G4) * E_ + k];
        g_wcat[idx] = __float2bfloat16(v);
    } else if (idx < NW + NH) {
        int i = idx - NW;
        int d = i / (G4 * H_);
        int rem = i % (G4 * H_);
        float v = d ? Whh_b[rem] : Whh_f[rem];
        g_whh[i] = __float2bfloat16(v);
    } else if (idx < NW + NH + 1024) {
        int n = idx - NW - NH;
        g_bias[n] = (n < G4) ? b_f[n] : b_b[n - G4];
    } else if (idx < NW + NH + 1024 + 512) {
        g_chunk_cnt[idx - NW - NH - 1024] = 0;
    } else if (idx == NW + NH + 1024 + 512) {
        g_tile_ctr = 0;
    }
}

// ---------------- K2: fused producer(GEMM)/consumer(LSTM) — unchanged ----------------
#define BM 128
#define BN 128
#define BK 32
#define SA 40
#define KITERS (KP / BK)   // 10
#define HS 136             // h_sm row stride in bf16

__global__ __launch_bounds__(512, 1) void k_main() {
    __shared__ __align__(16) char s_raw[40960];   // union: GEMM As/Bs  |  LSTM h_sm
    __shared__ int s_ti;

    const int bid = blockIdx.x;
    const int tid = threadIdx.x;

    if (bid < NPROD) {
        // ============ GEMM producer (work-stealing, 512 threads, 16 warps 4x4) ============
        __nv_bfloat16 (*As)[BM * SA] = (__nv_bfloat16(*)[BM * SA])s_raw;
        __nv_bfloat16 (*Bs)[BN * SA] = (__nv_bfloat16(*)[BN * SA])(s_raw + 2 * BM * SA * 2);

        const int warp = tid >> 5, lane = tid & 31;
        const int wm = warp >> 2, wn = warp & 3;       // 4m x 4n, warp tile 32x32
        const int lr = lane >> 2, lc = (lane & 3) * 2;
        const int ldr = tid >> 2, seg = tid & 3;
        const int lg = lane >> 3, lr8 = lane & 7;

        uint32_t aAddr[2][2], bAddr[2][2];
        #pragma unroll
        for (int st = 0; st < 2; st++) {
            #pragma unroll
            for (int mi = 0; mi < 2; mi++) {
                const int arow = wm * 32 + mi * 16 + lr8 + (lg & 1) * 8;
                const int acol = (lg >> 1) * 8;
                aAddr[st][mi] = (uint32_t)__cvta_generic_to_shared(&As[st][arow * SA + acol]);
            }
            #pragma unroll
            for (int kh = 0; kh < 2; kh++) {
                const int brow = wn * 32 + lg * 8 + lr8;
                bAddr[st][kh] = (uint32_t)__cvta_generic_to_shared(&Bs[st][brow * SA + kh * 8]);
            }
        }

        __syncthreads();
        if (tid == 0) s_ti = atomicAdd(&g_tile_ctr, 1);
        __syncthreads();
        int ti = s_ti;

        while (ti < NTILES) {
            int b, q, bx;
            if (ti < 2048) {
                b = ti >> 4; int sub = ti & 15; q = (sub < 8) ? 0 : 3; bx = sub & 7;
            } else {
                int r2 = ti - 2048; b = r2 >> 4; int sub = r2 & 15; q = (sub < 8) ? 1 : 2; bx = sub & 7;
            }
            const int m0 = b * 512 + q * 128;
            const int n0 = bx * 128;
            const int fb = b * 4 + q;

            float acc[2][4][4];
            #pragma unroll
            for (int a = 0; a < 2; a++)
                #pragma unroll
                for (int bb2 = 0; bb2 < 4; bb2++)
                    #pragma unroll
                    for (int c = 0; c < 4; c++) acc[a][bb2][c] = 0.0f;

            cp16(&As[0][ldr * SA + seg * 8], &g_emb[(size_t)(m0 + ldr) * KP + seg * 8]);
            cp16(&Bs[0][ldr * SA + seg * 8], &g_wcat[(size_t)(n0 + ldr) * KP + seg * 8]);
            cp_commit();

            for (int it = 0; it < KITERS; it++) {
                if (it + 1 < KITERS) {
                    const int kt = (it + 1) * BK;
                    const int st = (it + 1) & 1;
                    cp16(&As[st][ldr * SA + seg * 8], &g_emb[(size_t)(m0 + ldr) * KP + kt + seg * 8]);
                    cp16(&Bs[st][ldr * SA + seg * 8], &g_wcat[(size_t)(n0 + ldr) * KP + kt + seg * 8]);
                    cp_commit();
                    cp_wait<1>();
                } else {
                    cp_wait<0>();
                }
                __syncthreads();
                const int st = it & 1;
                #pragma unroll
                for (int ks = 0; ks < 2; ks++) {
                    const uint32_t koff = (uint32_t)(ks * 16) * 2;
                    uint32_t a[2][4];
                    #pragma unroll
                    for (int mi = 0; mi < 2; mi++)
                        asm volatile("ldmatrix.sync.aligned.m8n8.x4.shared.b16 {%0,%1,%2,%3}, [%4];\n"
                                     : "=r"(a[mi][0]), "=r"(a[mi][1]), "=r"(a[mi][2]), "=r"(a[mi][3])
                                     : "r"(aAddr[st][mi] + koff));
                    uint32_t bfr[4][2];
                    #pragma unroll
                    for (int kh = 0; kh < 2; kh++)
                        asm volatile("ldmatrix.sync.aligned.m8n8.x4.shared.b16 {%0,%1,%2,%3}, [%4];\n"
                                     : "=r"(bfr[0][kh]), "=r"(bfr[1][kh]),
                                       "=r"(bfr[2][kh]), "=r"(bfr[3][kh])
                                     : "r"(bAddr[st][kh] + koff));
                    #pragma unroll
                    for (int mi = 0; mi < 2; mi++)
                        #pragma unroll
                        for (int ni = 0; ni < 4; ni++) {
                            asm volatile(
                                "mma.sync.aligned.m16n8k16.row.col.f32.bf16.bf16.f32 "
                                "{%0,%1,%2,%3}, {%4,%5,%6,%7}, {%8,%9}, {%0,%1,%2,%3};\n"
                                : "+f"(acc[mi][ni][0]), "+f"(acc[mi][ni][1]),
                                  "+f"(acc[mi][ni][2]), "+f"(acc[mi][ni][3])
                                : "r"(a[mi][0]), "r"(a[mi][1]), "r"(a[mi][2]), "r"(a[mi][3]),
                                  "r"(bfr[ni][0]), "r"(bfr[ni][1]));
                        }
                }
                __syncthreads();
            }
            #pragma unroll
            for (int mi = 0; mi < 2; mi++) {
                #pragma unroll
                for (int ni = 0; ni < 4; ni++) {
                    int m = m0 + wm * 32 + mi * 16 + lr;
                    int n = n0 + wn * 32 + ni * 8 + lc;
                    int d = n >> 9, j = n & 511;
                    float bias0 = g_bias[n], bias1 = g_bias[n + 1];
                    {
                        int bb = m >> 9, ss = m & 511;
                        size_t base = (((size_t)(d * B_ + bb) * S_ + ss) * G4 + j);
                        *(float2*)&g_pre[base] = make_float2(acc[mi][ni][0] + bias0,
                                                             acc[mi][ni][1] + bias1);
                    }
                    {
                        int m2 = m + 8;
                        int bb = m2 >> 9, ss = m2 & 511;
                        size_t base = (((size_t)(d * B_ + bb) * S_ + ss) * G4 + j);
                        *(float2*)&g_pre[base] = make_float2(acc[mi][ni][2] + bias0,
                                                             acc[mi][ni][3] + bias1);
                    }
                }
            }
            __threadfence();
            __syncthreads();
            if (tid == 0) {
                atomicAdd(&g_chunk_cnt[fb], 1);
                s_ti = atomicAdd(&g_tile_ctr, 1);
            }
            __syncthreads();
            ti = s_ti;
        }
    } else {
        // ============ LSTM consumer (proven kernel + chunk waits) ============
        __nv_bfloat16 (*h_sm)[16][HS] = (__nv_bfloat16(*)[16][HS])s_raw;

        const int lbid = bid - NPROD;
        const int d   = lbid >> 4;
        const int bg  = lbid & 15;
        const int b0  = bg * 8;
        const int w = tid >> 5, l = tid & 31;
        const int r = l >> 2, cpair = (l & 3) * 2;

        uint32_t Bf[4][8][2];
        #pragma unroll
        for (int ni = 0; ni < 4; ni++) {
            const int n = w * 8 + ni * 128 + r;
            const __nv_bfloat16* src = &g_whh[((size_t)d * G4 + n) * H_ + cpair];
            #pragma unroll
            for (int tk = 0; tk < 8; tk++) {
                Bf[ni][tk][0] = *(const uint32_t*)&src[tk * 16];
                Bf[ni][tk][1] = *(const uint32_t*)&src[tk * 16 + 8];
            }
        }
        for (int i = tid; i < 2 * 16 * HS; i += 512)
            ((__nv_bfloat16*)h_sm)[i] = __float2bfloat16(0.0f);

        const int b  = b0 + r;
        const int m0 = w * 8 + cpair;
        const int sgn = d ? -1 : 1;
        const int se0 = d ? (S_ - 1) : 0;

        const float* preb = &g_pre[((size_t)(d * B_ + b) * S_ + se0) * G4 + m0];
        __nv_bfloat16* hout = &g_hcat[((size_t)b * S_ + se0) * 256 + d * H_ + m0];
        const int preb_step = sgn * G4;
        const int hout_step = sgn * 256;

        __syncthreads();

        {
            const int qc = d ? 3 : 0;
            if (tid < 8) {
                volatile int* cnt = (volatile int*)&g_chunk_cnt[(b0 + tid) * 4 + qc];
                while (*cnt < 8) { }
            }
            __syncthreads();
            __threadfence();
        }

        float2 pf[4];
        #pragma unroll
        for (int ni = 0; ni < 4; ni++)
            pf[ni] = *(const float2*)&preb[ni * 128];

        float cA = 0.0f, cB = 0.0f;
        const uint32_t abase0 =
            (uint32_t)__cvta_generic_to_shared(&h_sm[0][l & 15][(l >> 4) * 8]);

        int buf = 0;
        #pragma unroll 1
        for (int s = 0; s < S_; s++) {
            float acc[4][4];
            #pragma unroll
            for (int ni = 0; ni < 4; ni++) {
                acc[ni][0] = pf[ni].x; acc[ni][1] = pf[ni].y;
                acc[ni][2] = 0.0f;     acc[ni][3] = 0.0f;
            }
            if ((s & 127) == 127 && s != S_ - 1) {
                const int qn = d ? ((510 - s) >> 7) : ((s + 1) >> 7);
                if (tid < 8) {
                    volatile int* cnt = (volatile int*)&g_chunk_cnt[(b0 + tid) * 4 + qn];
                    while (*cnt < 8) { }
                }
                __syncthreads();
                __threadfence();
            }
            if (s < S_ - 1) preb += preb_step;
            #pragma unroll
            for (int ni = 0; ni < 4; ni++)
                pf[ni] = *(const float2*)&preb[ni * 128];

            const uint32_t abase = abase0 + (uint32_t)buf * (16 * HS * 2);
            #pragma unroll
            for (int tk = 0; tk < 8; tk++) {
                uint32_t a0, a1, a2, a3;
                asm volatile("ldmatrix.sync.aligned.m8n8.x4.shared.b16 {%0,%1,%2,%3}, [%4];\n"
                             : "=r"(a0), "=r"(a1), "=r"(a2), "=r"(a3)
                             : "r"(abase + tk * 32));
                #pragma unroll
                for (int ni = 0; ni < 4; ni++) {
                    asm volatile(
                        "mma.sync.aligned.m16n8k16.row.col.f32.bf16.bf16.f32 "
                        "{%0,%1,%2,%3}, {%4,%5,%6,%7}, {%8,%9}, {%0,%1,%2,%3};\n"
                        : "+f"(acc[ni][0]), "+f"(acc[ni][1]),
                          "+f"(acc[ni][2]), "+f"(acc[ni][3])
                        : "r"(a0), "r"(a1), "r"(a2), "r"(a3),
                          "r"(Bf[ni][tk][0]), "r"(Bf[ni][tk][1]));
                }
            }

            cA = sigf(acc[1][0]) * cA + sigf(acc[0][0]) * tanhapx(acc[2][0]);
            cB = sigf(acc[1][1]) * cB + sigf(acc[0][1]) * tanhapx(acc[2][1]);
            float hA = sigf(acc[3][0]) * tanhapx(cA);
            float hB = sigf(acc[3][1]) * tanhapx(cB);

            __nv_bfloat162 hpk = __floats2bfloat162_rn(hA, hB);
            *(__nv_bfloat162*)&h_sm[buf ^ 1][r][m0] = hpk;
            *(__nv_bfloat162*)hout = hpk;
            hout += hout_step;

            __syncthreads();
            buf ^= 1;
        }
    }
}

// ---------------- K4: fused output linear + CRF (wsm padded -> conflict-free) ----------------
#define WS 258   // wsm row stride in floats: 258%32=2 -> 12 t-rows hit distinct bank pairs

__global__ __launch_bounds__(256) void k_outcrf(const int* __restrict__ y0,
                                                const float* __restrict__ trans,
                                                const float* __restrict__ Wout,
                                                const float* __restrict__ bout,
                                                float* __restrict__ out) {
    __shared__ float ysm[S_][T_];        // 24576 B
    __shared__ __align__(8) float wsm[T_][WS];   // padded: no bank conflicts
    __shared__ float tsm[T_][T_];
    __shared__ float esm[T_][T_];
    __shared__ float gpart[7];
    __shared__ float zsm;

    const int b = blockIdx.x;
    const int tid = threadIdx.x;
    const int lane = tid & 31, wrp = tid >> 5;

    for (int i = tid; i < T_ * 256; i += 256) wsm[i >> 8][i & 255] = Wout[i];
    for (int i = tid; i < T_ * T_; i += 256) {
        float tv = trans[i];
        tsm[0][i] = tv;
        esm[0][i] = __expf(tv);    // exp(-1e4) = 0 exactly
    }
    if (tid < 7) gpart[tid] = 0.0f;
    __syncthreads();

    // ---- Phase 1: y = hcat @ Wout^T + bout ----
    const __nv_bfloat162* hbase = (const __nv_bfloat162*)&g_hcat[(size_t)b * S_ * 256];
    for (int idx = tid; idx < S_ * T_; idx += 256) {
        const int s = idx / T_, t = idx - s * T_;
        const __nv_bfloat162* hp = hbase + s * 128;
        const float2* wp = (const float2*)&wsm[t][0];
        float acc = bout[t];
        #pragma unroll 16
        for (int q = 0; q < 128; q++) {
            float2 h2 = __bfloat1622float2(hp[q]);
            float2 w2 = wp[q];
            acc += h2.x * w2.x + h2.y * w2.y;
        }
        ysm[s][t] = acc;
    }
    __syncthreads();

    // ---- Phase 2a: warps 1-7 compute gold path score ----
    if (wrp > 0) {
        const int* yb = &y0[b * S_];
        float g = 0.0f;
        for (int s = tid - 32; s < S_; s += 224) {
            int cur = yb[s];
            int prev = s ? yb[s - 1] : SOS_;
            g += ysm[s][cur] + tsm[cur][prev];
        }
        #pragma unroll
        for (int o = 16; o; o >>= 1) g += __shfl_xor_sync(0xffffffffu, g, o);
        if (lane == 0) gpart[wrp - 1] = g;
    }
    // ---- Phase 2b: warp 0 forward scan (exp-domain, lane-0 anchor) ----
    else {
        float e_row[T_];
        const int irow = (lane < T_) ? lane : 0;
        #pragma unroll
        for (int jj = 0; jj < T_; jj++) e_row[jj] = esm[irow][jj];

        float score = (lane < T_) ? tsm[irow][SOS_] + ysm[0][irow] : -1e30f;

        for (int s = 1; s < S_; s++) {
            float anchor = __shfl_sync(0xffffffffu, score, 0);
            float p = __expf(score - anchor);
            float Ssum = 0.0f;
            #pragma unroll
            for (int jj = 0; jj < T_; jj++)
                Ssum = fmaf(e_row[jj], __shfl_sync(0xffffffffu, p, jj), Ssum);
            float yv = ysm[s][irow];
            score = (lane < T_) ? anchor + __logf(Ssum) + yv : -1e30f;
        }
        float vz = (lane < T_) ? score + tsm[EOS_][irow] : -1e30f;
        float mz = vz;
        #pragma unroll
        for (int o = 16; o; o >>= 1) mz = fmaxf(mz, __shfl_xor_sync(0xffffffffu, mz, o));
        float ez = (lane < T_) ? __expf(vz - mz) : 0.0f;
        #pragma unroll
        for (int o = 16; o; o >>= 1) ez += __shfl_xor_sync(0xffffffffu, ez, o);
        if (lane == 0) zsm = mz + __logf(ez);
    }
    __syncthreads();
    if (tid == 0) {
        const int last = y0[b * S_ + S_ - 1];
        float gold = gpart[0] + gpart[1] + gpart[2] + gpart[3] + gpart[4] + gpart[5] + gpart[6]
                   + tsm[EOS_][last];
        out[b] = zsm - gold;
    }
}

// ---------------- launcher ----------------
extern "C" void kernel_launch(void* const* d_in, const int* in_sizes, int n_in,
                              void* d_out, int out_size) {
    const int*   x     = (const int*)d_in[0];
    const int*   y0    = (const int*)d_in[1];
    const float* embed = (const float*)d_in[2];
    const float* Wih_f = (const float*)d_in[3];
    const float* Whh_f = (const float*)d_in[4];
    const float* b_f   = (const float*)d_in[5];
    const float* Wih_b = (const float*)d_in[6];
    const float* Whh_b = (const float*)d_in[7];
    const float* b_b   = (const float*)d_in[8];
    const float* Wout  = (const float*)d_in[9];
    const float* bout  = (const float*)d_in[10];
    const float* trans = (const float*)d_in[11];
    float* out = (float*)d_out;

    k_prep_emb<<<(B_ * S_) / 16, 256>>>(x, embed);

    const int prep_total = 1024 * KP + 2 * G4 * H_ + 1024 + 512 + 1;
    k_prep_w<<<(prep_total + 255) / 256, 256>>>(Wih_f, Whh_f, b_f, Wih_b, Whh_b, b_b);

    k_main<<<NPROD + NCONS, 512>>>();

    k_outcrf<<<B_, 256>>>(y0, trans, Wout, bout, out);
}